// round 12
// baseline (speedup 1.0000x reference)
#include <cuda_runtime.h>
#include <cstdint>

// ---------------- problem constants ----------------
#define BB 4
#define NN 6
#define DD 41
#define FH 16
#define FW 44
#define CC 64
#define NX 200
#define NY 200
#define RAYS_PER_BN (FH*FW)        // 704
#define NRAYS (BB*NN*RAYS_PER_BN)  // 16896
#define SPATIAL (NX*NY)            // 40000
#define WORDS_PER_B (SPATIAL/32)   // 1250 bitmap words per batch

// depth split: 7 chunks of <=6 depths
#define NCHUNK 7
#define DCHUNK 6                   // chunk c covers [c*6, min(41, c*6+6))
#define NWARPS2 (NRAYS*NCHUNK/32)  // 3696 emission warps
#define RUNS_PER_WARP2 (32*DCHUNK) // 192 slots per warp region

#define BLKS_PER_CHUNK (NRAYS/256) // 66
#define RUN_BLOCKS (NCHUNK*BLKS_PER_CHUNK)  // 462
#define MAXRUN 4                   // max depths per emitted run record
#define CHUNK 8
#define BLKS_PER_SEG 2

// channel-last scratch accumulator: (B, NX*NY, C).
// INVARIANT: zero at entry (load-time zero init; out_write re-zeroes touched rows).
__device__ __align__(16) float g_scratch[BB * SPATIAL * CC];
// touched-voxel bitmap, 1 bit per (b, s). INVARIANT: zero at entry.
__device__ unsigned g_bitmap[BB * WORDS_PER_B];
// run records: rec.x = p_start | (count<<20), rec.y = voxel index b*SPATIAL+s
__device__ int2 g_runs[NWARPS2 * RUNS_PER_WARP2];
__device__ int  g_warp_count[NWARPS2];

// ---------------- 3x3 inverse (adjugate) ----------------
__device__ __forceinline__ void inv3(const float* m, float* o) {
    float a=m[0],b=m[1],c=m[2],d=m[3],e=m[4],f=m[5],g=m[6],h=m[7],i=m[8];
    float A  =  (e*i - f*h);
    float Bm = -(d*i - f*g);
    float Cm =  (d*h - e*g);
    float det = a*A + b*Bm + c*Cm;
    float inv = 1.0f / det;
    o[0] =  A*inv;
    o[1] = -(b*i - c*h)*inv;
    o[2] =  (b*f - c*e)*inv;
    o[3] =  Bm*inv;
    o[4] =  (a*i - c*g)*inv;
    o[5] = -(a*f - c*d)*inv;
    o[6] =  Cm*inv;
    o[7] = -(a*h - b*g)*inv;
    o[8] =  (a*e - b*d)*inv;
}

// ---------------- per-(ray, depth-chunk) walk -> runs + touched bitmap ----------------
// Block = 256 consecutive rays of one depth chunk; spans <=2 (b,n) groups.
// Threads 0/1 compute the (up to) two param sets into smem; all threads read.
__global__ void __launch_bounds__(256) run_kernel(
        const float* __restrict__ rots,
        const float* __restrict__ intrins,
        const float* __restrict__ post_rots,
        const float* __restrict__ trans,
        const float* __restrict__ post_trans) {
    __shared__ float sp[2][24];   // [slot][ cmb 0..8 | iPR 9..17 | pt 18..20 | t 21..23 ]

    int chnk = blockIdx.x / BLKS_PER_CHUNK;          // 0..6
    int blk  = blockIdx.x - chnk * BLKS_PER_CHUNK;   // 0..65
    int ray0 = blk * 256;
    int ray  = ray0 + threadIdx.x;                   // 0..16895
    int lane = threadIdx.x & 31;
    int wid  = (chnk * NRAYS + ray) >> 5;            // 0..3695
    int bn0  = ray0 / RAYS_PER_BN;

    if (threadIdx.x < 2) {
        int bnp = min(bn0 + (int)threadIdx.x, BB*NN - 1);
        float iK[9], iPR[9];
        inv3(intrins + bnp*9, iK);
        inv3(post_rots + bnp*9, iPR);
        const float* R = rots + bnp*9;
        float* o = sp[threadIdx.x];
        #pragma unroll
        for (int r = 0; r < 3; r++)
            #pragma unroll
            for (int c = 0; c < 3; c++)
                o[r*3+c] = R[r*3+0]*iK[0*3+c] + R[r*3+1]*iK[1*3+c] + R[r*3+2]*iK[2*3+c];
        #pragma unroll
        for (int k = 0; k < 9; k++) o[9+k] = iPR[k];
        o[18] = post_trans[bnp*3+0]; o[19] = post_trans[bnp*3+1]; o[20] = post_trans[bnp*3+2];
        o[21] = trans[bnp*3+0];      o[22] = trans[bnp*3+1];      o[23] = trans[bnp*3+2];
    }
    __syncthreads();

    int bn = ray / RAYS_PER_BN;
    int hw = ray - bn * RAYS_PER_BN;
    int h  = hw / FW;
    int w  = hw - h * FW;
    int b  = bn / NN;
    const float* prm = sp[bn - bn0];

    int d0 = chnk * DCHUNK;
    int d1 = min(DD, d0 + DCHUNK);

    float cmb0=prm[0], cmb1=prm[1], cmb2=prm[2];
    float cmb3=prm[3], cmb4=prm[4], cmb5=prm[5];
    float cmb6=prm[6], cmb7=prm[7], cmb8=prm[8];
    float t0=prm[21], t1=prm[22], t2=prm[23];

    float u = (float)w * (351.0f / 43.0f);
    float v = (float)h * (127.0f / 15.0f);
    float px  = u - prm[18];
    float py  = v - prm[19];
    float pz0 = (4.0f + (float)d0) - prm[20];

    float qx  = prm[ 9]*px + prm[10]*py + prm[11]*pz0;
    float qy  = prm[12]*px + prm[13]*py + prm[14]*pz0;
    float qz  = prm[15]*px + prm[16]*py + prm[17]*pz0;
    float dqx = prm[11], dqy = prm[14], dqz = prm[17];

    int2* region = g_runs + wid * RUNS_PER_WARP2;
    unsigned lt_mask = (1u << lane) - 1u;

    int obase = b * SPATIAL;
    int cur = -1;
    int curStart = d0;
    int wcnt = 0;                  // warp-uniform running count

    #pragma unroll 1
    for (int d = d0; d < d1; d++) {
        float sx = qx * qz;
        float sy = qy * qz;
        float gx = cmb0*sx + cmb1*sy + cmb2*qz + t0;
        float gy = cmb3*sx + cmb4*sy + cmb5*qz + t1;
        float gz = cmb6*sx + cmb7*sy + cmb8*qz + t2;

        int ix = (int)((gx + 50.0f) / 0.5f);
        int iy = (int)((gy + 50.0f) / 0.5f);
        int iz = (int)((gz + 10.0f) / 20.0f);

        int o = -1;
        if (ix >= 0 && ix < NX && iy >= 0 && iy < NY && iz == 0)
            o = obase + ix * NY + iy;          // voxel index

        bool newvox = (o != cur);
        if (newvox && o >= 0)
            atomicOr(&g_bitmap[o >> 5], 1u << (o & 31));

        bool flush = (cur >= 0) && (newvox || (d - curStart) == MAXRUN);
        unsigned bal = __ballot_sync(0xffffffffu, flush);
        if (flush) {
            int p0 = (bn*DD + curStart) * RAYS_PER_BN + hw;
            region[wcnt + __popc(bal & lt_mask)] =
                make_int2(p0 | ((d - curStart) << 20), cur);
        }
        wcnt += __popc(bal);
        if (flush && !newvox) curStart = d;     // split long run, same voxel
        if (newvox) { cur = o; curStart = d; }

        qx += dqx; qy += dqy; qz += dqz;
    }

    {   // final flush
        bool flush = (cur >= 0);
        unsigned bal = __ballot_sync(0xffffffffu, flush);
        if (flush) {
            int p0 = (bn*DD + curStart) * RAYS_PER_BN + hw;
            region[wcnt + __popc(bal & lt_mask)] =
                make_int2(p0 | ((d1 - curStart) << 20), cur);
        }
        wcnt += __popc(bal);
    }
    if (lane == 0) g_warp_count[wid] = wcnt;
}

// ---------------- run scatter: depth-major loads, coalesced red.v2 flush ----------------
// Lane l owns channels (2l, 2l+1) — contiguous in the channel-last scratch,
// so each flush is 32 x red.global.add.v2.f32 covering 256 contiguous bytes.
__global__ void __launch_bounds__(256) scatter_runs_kernel(
        const float* __restrict__ x) {
    int seg  = blockIdx.x / BLKS_PER_SEG;
    int sub  = blockIdx.x - seg * BLKS_PER_SEG;
    int cnt  = g_warp_count[seg];
    if (cnt == 0) return;
    const int2* runs = g_runs + seg * RUNS_PER_WARP2;
    int wrp  = threadIdx.x >> 5;
    int lane = threadIdx.x & 31;
    int gw   = sub * 8 + wrp;          // warps serving this segment
    const float2* xf2 = reinterpret_cast<const float2*>(x);

    for (int base = gw * CHUNK; base < cnt; base += BLKS_PER_SEG * 8 * CHUNK) {
        int n = min(CHUNK, cnt - base);

        // cooperative record fetch: lanes 0..7 each load one rec, broadcast
        int2 myrec = make_int2(0, -1);
        if (lane < n) myrec = __ldg(runs + base + lane);
        int rx[CHUNK], ry[CHUNK];
        #pragma unroll
        for (int i = 0; i < CHUNK; i++) {
            rx[i] = __shfl_sync(0xffffffffu, myrec.x, i);
            ry[i] = __shfl_sync(0xffffffffu, myrec.y, i);
        }

        // depth-major accumulation: level-j loads for all runs are independent
        float2 acc[CHUNK];
        #pragma unroll
        for (int i = 0; i < CHUNK; i++) acc[i] = make_float2(0.f, 0.f);

        #pragma unroll
        for (int j = 0; j < MAXRUN; j++) {
            float2 v[CHUNK];
            #pragma unroll
            for (int i = 0; i < CHUNK; i++) {
                int c = rx[i] >> 20;
                if (i < n && j < c) {
                    int p = (rx[i] & 0xFFFFF) + j * RAYS_PER_BN;
                    v[i] = __ldg(xf2 + (size_t)p * (CC/2) + lane);
                }
            }
            #pragma unroll
            for (int i = 0; i < CHUNK; i++) {
                int c = rx[i] >> 20;
                if (i < n && j < c) { acc[i].x += v[i].x; acc[i].y += v[i].y; }
            }
        }

        // merge consecutive same-voxel runs, then coalesced vector-red flush
        int curOff = -1;
        float2 a = make_float2(0.f, 0.f);
        #pragma unroll
        for (int i = 0; i < CHUNK; i++) {
            if (i >= n) break;
            if (ry[i] != curOff) {
                if (curOff >= 0) {
                    float* dp = g_scratch + (size_t)curOff * CC + 2*lane;
                    asm volatile("red.global.add.v2.f32 [%0], {%1, %2};"
                                 :: "l"(dp), "f"(a.x), "f"(a.y) : "memory");
                }
                curOff = ry[i];
                a = make_float2(0.f, 0.f);
            }
            a.x += acc[i].x; a.y += acc[i].y;
        }
        if (curOff >= 0) {
            float* dp = g_scratch + (size_t)curOff * CC + 2*lane;
            asm volatile("red.global.add.v2.f32 [%0], {%1, %2};"
                         :: "l"(dp), "f"(a.x), "f"(a.y) : "memory");
        }
    }
}

// ---------------- output write: zeros + touched-voxel gather + cleanup ----------------
__global__ void __launch_bounds__(256) out_write_kernel(float* __restrict__ out) {
    __shared__ unsigned sw;
    int b    = blockIdx.y;
    int tile = blockIdx.x;              // 0..1249
    int tid  = threadIdx.x;
    int lane = tid & 31;
    int wrp  = tid >> 5;                // 0..7

    if (tid == 0) sw = g_bitmap[b * WORDS_PER_B + tile];
    __syncthreads();
    unsigned word = sw;

    int s0 = tile * 32;
    float* sc = g_scratch + ((size_t)b * SPATIAL + s0) * CC;

    float vals[8];
    if ((word >> lane) & 1u) {
        const float4* p = reinterpret_cast<const float4*>(sc + lane*CC + wrp*8);
        float4 v0 = p[0];
        float4 v1 = p[1];
        vals[0]=v0.x; vals[1]=v0.y; vals[2]=v0.z; vals[3]=v0.w;
        vals[4]=v1.x; vals[5]=v1.y; vals[6]=v1.z; vals[7]=v1.w;
    } else {
        #pragma unroll
        for (int k = 0; k < 8; k++) vals[k] = 0.f;
    }

    float* op = out + ((size_t)b * CC + wrp*8) * SPATIAL + s0 + lane;
    #pragma unroll
    for (int k = 0; k < 8; k++)
        op[(size_t)k * SPATIAL] = vals[k];

    if (word == 0) return;
    __syncthreads();

    // re-zero touched scratch rows: thread t -> voxel t>>3, floats [(t&7)*8, +8)
    int vox = tid >> 3;
    if ((word >> vox) & 1u) {
        float4* p = reinterpret_cast<float4*>(sc + vox*CC + (tid & 7)*8);
        const float4 z4 = make_float4(0.f, 0.f, 0.f, 0.f);
        p[0] = z4;
        p[1] = z4;
    }
    if (tid == 0) g_bitmap[b * WORDS_PER_B + tile] = 0u;
}

// ---------------- launch ----------------
extern "C" void kernel_launch(void* const* d_in, const int* in_sizes, int n_in,
                              void* d_out, int out_size) {
    const float* x          = (const float*)d_in[0];
    const float* rots       = (const float*)d_in[1];
    const float* trans      = (const float*)d_in[2];
    const float* intrins    = (const float*)d_in[3];
    const float* post_rots  = (const float*)d_in[4];
    const float* post_trans = (const float*)d_in[5];
    float* out = (float*)d_out;

    // 1. ray walk (7 depth-chunks per ray) -> run list + touched bitmap
    run_kernel<<<RUN_BLOCKS, 256>>>(rots, intrins, post_rots, trans, post_trans);

    // 2. feature accumulate into channel-last scratch (coalesced vector reds)
    scatter_runs_kernel<<<NWARPS2 * BLKS_PER_SEG, 256>>>(x);

    // 3. write output (zeros + gather), restore scratch/bitmap invariants
    out_write_kernel<<<dim3(WORDS_PER_B, BB), 256>>>(out);
}

// round 13
// speedup vs baseline: 1.0816x; 1.0816x over previous
#include <cuda_runtime.h>
#include <cstdint>

// ---------------- problem constants ----------------
#define BB 4
#define NN 6
#define DD 41
#define FH 16
#define FW 44
#define CC 64
#define NX 200
#define NY 200
#define RAYS_PER_BN (FH*FW)        // 704
#define NRAYS (BB*NN*RAYS_PER_BN)  // 16896
#define SPATIAL (NX*NY)            // 40000
#define WORDS_PER_B (SPATIAL/32)   // 1250 bitmap words per batch

// depth split: 4 chunks of <=11 depths (R11 proven config)
#define NCHUNK 4
#define DCHUNK 11                  // chunk c covers [c*11, min(41, c*11+11))
#define NWARPS2 (NRAYS*NCHUNK/32)  // 2112 emission warps
#define RUNS_PER_WARP2 (32*DCHUNK) // 352 slots per warp region

#define BLKS_PER_CHUNK (NRAYS/256) // 66
#define RUN_BLOCKS (NCHUNK*BLKS_PER_CHUNK)  // 264
#define MAXRUN 4                   // max depths per emitted run record
#define CHUNK 8
#define BLKS_PER_SEG 2

// channel-last scratch accumulator: (B, NX*NY, C).
// INVARIANT: zero at entry (load-time zero init; out_write re-zeroes touched rows).
__device__ __align__(16) float g_scratch[BB * SPATIAL * CC];
// touched-voxel bitmap, 1 bit per (b, s). INVARIANT: zero at entry.
__device__ unsigned g_bitmap[BB * WORDS_PER_B];
// run records: rec.x = p_start | (count<<20), rec.y = voxel index b*SPATIAL+s
__device__ int2 g_runs[NWARPS2 * RUNS_PER_WARP2];
__device__ int  g_warp_count[NWARPS2];

// ---------------- 3x3 inverse (adjugate) ----------------
__device__ __forceinline__ void inv3(const float* m, float* o) {
    float a=m[0],b=m[1],c=m[2],d=m[3],e=m[4],f=m[5],g=m[6],h=m[7],i=m[8];
    float A  =  (e*i - f*h);
    float Bm = -(d*i - f*g);
    float Cm =  (d*h - e*g);
    float det = a*A + b*Bm + c*Cm;
    float inv = 1.0f / det;
    o[0] =  A*inv;
    o[1] = -(b*i - c*h)*inv;
    o[2] =  (b*f - c*e)*inv;
    o[3] =  Bm*inv;
    o[4] =  (a*i - c*g)*inv;
    o[5] = -(a*f - c*d)*inv;
    o[6] =  Cm*inv;
    o[7] = -(a*h - b*g)*inv;
    o[8] =  (a*e - b*d)*inv;
}

// ---------------- per-(ray, depth-chunk) walk -> runs ----------------
// Block = 256 consecutive rays of one depth chunk; spans <=2 (b,n) groups.
// Threads 0/1 compute the (up to) two param sets into smem; all threads read.
// NOTE: no bitmap marking here — scatter marks it at flush time.
__global__ void __launch_bounds__(256) run_kernel(
        const float* __restrict__ rots,
        const float* __restrict__ intrins,
        const float* __restrict__ post_rots,
        const float* __restrict__ trans,
        const float* __restrict__ post_trans) {
    __shared__ float sp[2][24];   // [slot][ cmb 0..8 | iPR 9..17 | pt 18..20 | t 21..23 ]

    int chnk = blockIdx.x / BLKS_PER_CHUNK;          // 0..3
    int blk  = blockIdx.x - chnk * BLKS_PER_CHUNK;   // 0..65
    int ray0 = blk * 256;
    int ray  = ray0 + threadIdx.x;                   // 0..16895
    int lane = threadIdx.x & 31;
    int wid  = (chnk * NRAYS + ray) >> 5;            // 0..2111
    int bn0  = ray0 / RAYS_PER_BN;

    if (threadIdx.x < 2) {
        int bnp = min(bn0 + (int)threadIdx.x, BB*NN - 1);
        float iK[9], iPR[9];
        inv3(intrins + bnp*9, iK);
        inv3(post_rots + bnp*9, iPR);
        const float* R = rots + bnp*9;
        float* o = sp[threadIdx.x];
        #pragma unroll
        for (int r = 0; r < 3; r++)
            #pragma unroll
            for (int c = 0; c < 3; c++)
                o[r*3+c] = R[r*3+0]*iK[0*3+c] + R[r*3+1]*iK[1*3+c] + R[r*3+2]*iK[2*3+c];
        #pragma unroll
        for (int k = 0; k < 9; k++) o[9+k] = iPR[k];
        o[18] = post_trans[bnp*3+0]; o[19] = post_trans[bnp*3+1]; o[20] = post_trans[bnp*3+2];
        o[21] = trans[bnp*3+0];      o[22] = trans[bnp*3+1];      o[23] = trans[bnp*3+2];
    }
    __syncthreads();

    int bn = ray / RAYS_PER_BN;
    int hw = ray - bn * RAYS_PER_BN;
    int h  = hw / FW;
    int w  = hw - h * FW;
    int b  = bn / NN;
    const float* prm = sp[bn - bn0];

    int d0 = chnk * DCHUNK;
    int d1 = min(DD, d0 + DCHUNK);

    float cmb0=prm[0], cmb1=prm[1], cmb2=prm[2];
    float cmb3=prm[3], cmb4=prm[4], cmb5=prm[5];
    float cmb6=prm[6], cmb7=prm[7], cmb8=prm[8];
    float t0=prm[21], t1=prm[22], t2=prm[23];

    float u = (float)w * (351.0f / 43.0f);
    float v = (float)h * (127.0f / 15.0f);
    float px  = u - prm[18];
    float py  = v - prm[19];
    float pz0 = (4.0f + (float)d0) - prm[20];

    float qx  = prm[ 9]*px + prm[10]*py + prm[11]*pz0;
    float qy  = prm[12]*px + prm[13]*py + prm[14]*pz0;
    float qz  = prm[15]*px + prm[16]*py + prm[17]*pz0;
    float dqx = prm[11], dqy = prm[14], dqz = prm[17];

    int2* region = g_runs + wid * RUNS_PER_WARP2;
    unsigned lt_mask = (1u << lane) - 1u;

    int obase = b * SPATIAL;
    int cur = -1;
    int curStart = d0;
    int wcnt = 0;                  // warp-uniform running count

    #pragma unroll 1
    for (int d = d0; d < d1; d++) {
        float sx = qx * qz;
        float sy = qy * qz;
        float gx = cmb0*sx + cmb1*sy + cmb2*qz + t0;
        float gy = cmb3*sx + cmb4*sy + cmb5*qz + t1;
        float gz = cmb6*sx + cmb7*sy + cmb8*qz + t2;

        int ix = (int)((gx + 50.0f) / 0.5f);
        int iy = (int)((gy + 50.0f) / 0.5f);
        int iz = (int)((gz + 10.0f) / 20.0f);

        int o = -1;
        if (ix >= 0 && ix < NX && iy >= 0 && iy < NY && iz == 0)
            o = obase + ix * NY + iy;          // voxel index

        bool newvox = (o != cur);
        bool flush  = (cur >= 0) && (newvox || (d - curStart) == MAXRUN);
        unsigned bal = __ballot_sync(0xffffffffu, flush);
        if (flush) {
            int p0 = (bn*DD + curStart) * RAYS_PER_BN + hw;
            region[wcnt + __popc(bal & lt_mask)] =
                make_int2(p0 | ((d - curStart) << 20), cur);
        }
        wcnt += __popc(bal);
        if (flush && !newvox) curStart = d;     // split long run, same voxel
        if (newvox) { cur = o; curStart = d; }

        qx += dqx; qy += dqy; qz += dqz;
    }

    {   // final flush
        bool flush = (cur >= 0);
        unsigned bal = __ballot_sync(0xffffffffu, flush);
        if (flush) {
            int p0 = (bn*DD + curStart) * RAYS_PER_BN + hw;
            region[wcnt + __popc(bal & lt_mask)] =
                make_int2(p0 | ((d1 - curStart) << 20), cur);
        }
        wcnt += __popc(bal);
    }
    if (lane == 0) g_warp_count[wid] = wcnt;
}

// ---------------- run scatter: depth-major loads, coalesced red.v2 flush ----------------
// Lane l owns channels (2l, 2l+1) — contiguous in the channel-last scratch,
// so each flush is 32 x red.global.add.v2.f32 covering 256 contiguous bytes.
// Lane 0 additionally marks the voxel in the touched bitmap.
__global__ void __launch_bounds__(256) scatter_runs_kernel(
        const float* __restrict__ x) {
    int seg  = blockIdx.x / BLKS_PER_SEG;
    int sub  = blockIdx.x - seg * BLKS_PER_SEG;
    int cnt  = g_warp_count[seg];
    if (cnt == 0) return;
    const int2* runs = g_runs + seg * RUNS_PER_WARP2;
    int wrp  = threadIdx.x >> 5;
    int lane = threadIdx.x & 31;
    int gw   = sub * 8 + wrp;          // warps serving this segment
    const float2* xf2 = reinterpret_cast<const float2*>(x);

    for (int base = gw * CHUNK; base < cnt; base += BLKS_PER_SEG * 8 * CHUNK) {
        int n = min(CHUNK, cnt - base);

        // cooperative record fetch: lanes 0..7 each load one rec, broadcast
        int2 myrec = make_int2(0, -1);
        if (lane < n) myrec = __ldg(runs + base + lane);
        int rx[CHUNK], ry[CHUNK];
        #pragma unroll
        for (int i = 0; i < CHUNK; i++) {
            rx[i] = __shfl_sync(0xffffffffu, myrec.x, i);
            ry[i] = __shfl_sync(0xffffffffu, myrec.y, i);
        }

        // depth-major accumulation: level-j loads for all runs are independent
        float2 acc[CHUNK];
        #pragma unroll
        for (int i = 0; i < CHUNK; i++) acc[i] = make_float2(0.f, 0.f);

        #pragma unroll
        for (int j = 0; j < MAXRUN; j++) {
            float2 v[CHUNK];
            #pragma unroll
            for (int i = 0; i < CHUNK; i++) {
                int c = rx[i] >> 20;
                if (i < n && j < c) {
                    int p = (rx[i] & 0xFFFFF) + j * RAYS_PER_BN;
                    v[i] = __ldg(xf2 + (size_t)p * (CC/2) + lane);
                }
            }
            #pragma unroll
            for (int i = 0; i < CHUNK; i++) {
                int c = rx[i] >> 20;
                if (i < n && j < c) { acc[i].x += v[i].x; acc[i].y += v[i].y; }
            }
        }

        // merge consecutive same-voxel runs, then coalesced vector-red flush
        int curOff = -1;
        float2 a = make_float2(0.f, 0.f);
        #pragma unroll
        for (int i = 0; i < CHUNK; i++) {
            if (i >= n) break;
            if (ry[i] != curOff) {
                if (curOff >= 0) {
                    float* dp = g_scratch + (size_t)curOff * CC + 2*lane;
                    asm volatile("red.global.add.v2.f32 [%0], {%1, %2};"
                                 :: "l"(dp), "f"(a.x), "f"(a.y) : "memory");
                    if (lane == 0)
                        atomicOr(&g_bitmap[curOff >> 5], 1u << (curOff & 31));
                }
                curOff = ry[i];
                a = make_float2(0.f, 0.f);
            }
            a.x += acc[i].x; a.y += acc[i].y;
        }
        if (curOff >= 0) {
            float* dp = g_scratch + (size_t)curOff * CC + 2*lane;
            asm volatile("red.global.add.v2.f32 [%0], {%1, %2};"
                         :: "l"(dp), "f"(a.x), "f"(a.y) : "memory");
            if (lane == 0)
                atomicOr(&g_bitmap[curOff >> 5], 1u << (curOff & 31));
        }
    }
}

// ---------------- output write: zeros + touched-voxel gather + cleanup ----------------
__global__ void __launch_bounds__(256) out_write_kernel(float* __restrict__ out) {
    __shared__ unsigned sw;
    int b    = blockIdx.y;
    int tile = blockIdx.x;              // 0..1249
    int tid  = threadIdx.x;
    int lane = tid & 31;
    int wrp  = tid >> 5;                // 0..7

    if (tid == 0) sw = g_bitmap[b * WORDS_PER_B + tile];
    __syncthreads();
    unsigned word = sw;

    int s0 = tile * 32;
    float* sc = g_scratch + ((size_t)b * SPATIAL + s0) * CC;

    float vals[8];
    if ((word >> lane) & 1u) {
        const float4* p = reinterpret_cast<const float4*>(sc + lane*CC + wrp*8);
        float4 v0 = p[0];
        float4 v1 = p[1];
        vals[0]=v0.x; vals[1]=v0.y; vals[2]=v0.z; vals[3]=v0.w;
        vals[4]=v1.x; vals[5]=v1.y; vals[6]=v1.z; vals[7]=v1.w;
    } else {
        #pragma unroll
        for (int k = 0; k < 8; k++) vals[k] = 0.f;
    }

    float* op = out + ((size_t)b * CC + wrp*8) * SPATIAL + s0 + lane;
    #pragma unroll
    for (int k = 0; k < 8; k++)
        op[(size_t)k * SPATIAL] = vals[k];

    if (word == 0) return;
    __syncthreads();

    // re-zero touched scratch rows: thread t -> voxel t>>3, floats [(t&7)*8, +8)
    int vox = tid >> 3;
    if ((word >> vox) & 1u) {
        float4* p = reinterpret_cast<float4*>(sc + vox*CC + (tid & 7)*8);
        const float4 z4 = make_float4(0.f, 0.f, 0.f, 0.f);
        p[0] = z4;
        p[1] = z4;
    }
    if (tid == 0) g_bitmap[b * WORDS_PER_B + tile] = 0u;
}

// ---------------- launch ----------------
extern "C" void kernel_launch(void* const* d_in, const int* in_sizes, int n_in,
                              void* d_out, int out_size) {
    const float* x          = (const float*)d_in[0];
    const float* rots       = (const float*)d_in[1];
    const float* trans      = (const float*)d_in[2];
    const float* intrins    = (const float*)d_in[3];
    const float* post_rots  = (const float*)d_in[4];
    const float* post_trans = (const float*)d_in[5];
    float* out = (float*)d_out;

    // 1. ray walk (4 depth-chunks per ray) -> run list
    run_kernel<<<RUN_BLOCKS, 256>>>(rots, intrins, post_rots, trans, post_trans);

    // 2. feature accumulate into channel-last scratch + bitmap marking
    scatter_runs_kernel<<<NWARPS2 * BLKS_PER_SEG, 256>>>(x);

    // 3. write output (zeros + gather), restore scratch/bitmap invariants
    out_write_kernel<<<dim3(WORDS_PER_B, BB), 256>>>(out);
}

// round 15
// speedup vs baseline: 1.0829x; 1.0012x over previous
#include <cuda_runtime.h>
#include <cstdint>

// ---------------- problem constants ----------------
#define BB 4
#define NN 6
#define DD 41
#define FH 16
#define FW 44
#define CC 64
#define NX 200
#define NY 200
#define RAYS_PER_BN (FH*FW)        // 704
#define NRAYS (BB*NN*RAYS_PER_BN)  // 16896
#define SPATIAL (NX*NY)            // 40000
#define WORDS_PER_B (SPATIAL/32)   // 1250 bitmap words per batch

// depth split: 4 chunks of <=11 depths
#define NCHUNK 4
#define DCHUNK 11                  // chunk c covers [c*11, min(41, c*11+11))
#define NWARPS2 (NRAYS*NCHUNK/32)  // 2112 emission warps
#define RUNS_PER_WARP2 (32*DCHUNK) // 352 slots per warp region

#define BLKS_PER_CHUNK (NRAYS/256) // 66
#define RUN_BLOCKS (NCHUNK*BLKS_PER_CHUNK)  // 264
#define ZERO_BLOCKS 2560           // 2560*256*4 float4 = 2,621,440 >= 2,560,000
#define ZERO_STRIDE (ZERO_BLOCKS*256)
#define OUT_FLOAT4 (BB*CC*SPATIAL/4)   // 2,560,000
#define MAXRUN 4                   // max depths per emitted run record
#define CHUNK 8
#define BLKS_PER_SEG 2

// channel-last scratch accumulator: (B, NX*NY, C).
// INVARIANT: zero at entry (load-time zero init; out_touched re-zeroes touched rows).
__device__ __align__(16) float g_scratch[BB * SPATIAL * CC];
// touched-voxel bitmap, 1 bit per (b, s). INVARIANT: zero at entry.
__device__ unsigned g_bitmap[BB * WORDS_PER_B];
// run records: rec.x = p_start | (count<<20), rec.y = voxel index b*SPATIAL+s
__device__ int2 g_runs[NWARPS2 * RUNS_PER_WARP2];
__device__ int  g_warp_count[NWARPS2];

// ---------------- 3x3 inverse (adjugate) ----------------
__device__ __forceinline__ void inv3(const float* m, float* o) {
    float a=m[0],b=m[1],c=m[2],d=m[3],e=m[4],f=m[5],g=m[6],h=m[7],i=m[8];
    float A  =  (e*i - f*h);
    float Bm = -(d*i - f*g);
    float Cm =  (d*h - e*g);
    float det = a*A + b*Bm + c*Cm;
    float inv = 1.0f / det;
    o[0] =  A*inv;
    o[1] = -(b*i - c*h)*inv;
    o[2] =  (b*f - c*e)*inv;
    o[3] =  Bm*inv;
    o[4] =  (a*i - c*g)*inv;
    o[5] = -(a*f - c*d)*inv;
    o[6] =  Cm*inv;
    o[7] = -(a*h - b*g)*inv;
    o[8] =  (a*e - b*d)*inv;
}

// ---------------- fused: ray walk (blocks 0..263) + output zero (rest) ----------------
__global__ void __launch_bounds__(256) run_zero_kernel(
        const float* __restrict__ rots,
        const float* __restrict__ intrins,
        const float* __restrict__ post_rots,
        const float* __restrict__ trans,
        const float* __restrict__ post_trans,
        float4* __restrict__ out4) {
    if (blockIdx.x >= RUN_BLOCKS) {
        // ---- zero path: 4 strided float4 stores per thread ----
        int idx = (blockIdx.x - RUN_BLOCKS) * 256 + threadIdx.x;
        const float4 z4 = make_float4(0.f, 0.f, 0.f, 0.f);
        #pragma unroll
        for (int k = 0; k < 4; k++) {
            int j = idx + k * ZERO_STRIDE;
            if (j < OUT_FLOAT4) out4[j] = z4;
        }
        return;
    }

    // ---- ray-walk path ----
    __shared__ float sp[2][24];   // [slot][ cmb 0..8 | iPR 9..17 | pt 18..20 | t 21..23 ]

    int chnk = blockIdx.x / BLKS_PER_CHUNK;          // 0..3
    int blk  = blockIdx.x - chnk * BLKS_PER_CHUNK;   // 0..65
    int ray0 = blk * 256;
    int ray  = ray0 + threadIdx.x;                   // 0..16895
    int lane = threadIdx.x & 31;
    int wid  = (chnk * NRAYS + ray) >> 5;            // 0..2111
    int bn0  = ray0 / RAYS_PER_BN;
    int d0   = chnk * DCHUNK;
    int d1   = min(DD, d0 + DCHUNK);

    if (threadIdx.x < 2) {
        int bnp = min(bn0 + (int)threadIdx.x, BB*NN - 1);
        float iK[9], iPR[9];
        inv3(intrins + bnp*9, iK);
        inv3(post_rots + bnp*9, iPR);
        const float* R = rots + bnp*9;
        float* o = sp[threadIdx.x];
        #pragma unroll
        for (int r = 0; r < 3; r++)
            #pragma unroll
            for (int c = 0; c < 3; c++)
                o[r*3+c] = R[r*3+0]*iK[0*3+c] + R[r*3+1]*iK[1*3+c] + R[r*3+2]*iK[2*3+c];
        #pragma unroll
        for (int k = 0; k < 9; k++) o[9+k] = iPR[k];
        o[18] = post_trans[bnp*3+0]; o[19] = post_trans[bnp*3+1]; o[20] = post_trans[bnp*3+2];
        o[21] = trans[bnp*3+0];      o[22] = trans[bnp*3+1];      o[23] = trans[bnp*3+2];
    }
    __syncthreads();

    int bn = ray / RAYS_PER_BN;
    int hw = ray - bn * RAYS_PER_BN;
    int h  = hw / FW;
    int w  = hw - h * FW;
    int b  = bn / NN;
    const float* prm = sp[bn - bn0];

    float cmb0=prm[0], cmb1=prm[1], cmb2=prm[2];
    float cmb3=prm[3], cmb4=prm[4], cmb5=prm[5];
    float cmb6=prm[6], cmb7=prm[7], cmb8=prm[8];
    float t0=prm[21], t1=prm[22], t2=prm[23];

    float u = (float)w * (351.0f / 43.0f);
    float v = (float)h * (127.0f / 15.0f);
    float px  = u - prm[18];
    float py  = v - prm[19];
    float pz0 = (4.0f + (float)d0) - prm[20];

    float qx  = prm[ 9]*px + prm[10]*py + prm[11]*pz0;
    float qy  = prm[12]*px + prm[13]*py + prm[14]*pz0;
    float qz  = prm[15]*px + prm[16]*py + prm[17]*pz0;
    float dqx = prm[11], dqy = prm[14], dqz = prm[17];

    int2* region = g_runs + wid * RUNS_PER_WARP2;
    unsigned lt_mask = (1u << lane) - 1u;

    int obase = b * SPATIAL;
    int cur = -1;
    int curStart = d0;
    int wcnt = 0;                  // warp-uniform running count

    #pragma unroll 1
    for (int d = d0; d < d1; d++) {
        float sx = qx * qz;
        float sy = qy * qz;
        float gx = cmb0*sx + cmb1*sy + cmb2*qz + t0;
        float gy = cmb3*sx + cmb4*sy + cmb5*qz + t1;
        float gz = cmb6*sx + cmb7*sy + cmb8*qz + t2;

        int ix = (int)((gx + 50.0f) / 0.5f);
        int iy = (int)((gy + 50.0f) / 0.5f);
        int iz = (int)((gz + 10.0f) / 20.0f);

        int o = -1;
        if (ix >= 0 && ix < NX && iy >= 0 && iy < NY && iz == 0)
            o = obase + ix * NY + iy;          // voxel index

        bool newvox = (o != cur);
        bool flush  = (cur >= 0) && (newvox || (d - curStart) == MAXRUN);
        unsigned bal = __ballot_sync(0xffffffffu, flush);
        if (flush) {
            int p0 = (bn*DD + curStart) * RAYS_PER_BN + hw;
            region[wcnt + __popc(bal & lt_mask)] =
                make_int2(p0 | ((d - curStart) << 20), cur);
        }
        wcnt += __popc(bal);
        if (flush && !newvox) curStart = d;     // split long run, same voxel
        if (newvox) { cur = o; curStart = d; }

        qx += dqx; qy += dqy; qz += dqz;
    }

    {   // final flush
        bool flush = (cur >= 0);
        unsigned bal = __ballot_sync(0xffffffffu, flush);
        if (flush) {
            int p0 = (bn*DD + curStart) * RAYS_PER_BN + hw;
            region[wcnt + __popc(bal & lt_mask)] =
                make_int2(p0 | ((d1 - curStart) << 20), cur);
        }
        wcnt += __popc(bal);
    }
    if (lane == 0) g_warp_count[wid] = wcnt;
}

// ---------------- run scatter: depth-major loads, coalesced red.v2 flush ----------------
// Lane l owns channels (2l, 2l+1) — contiguous in the channel-last scratch,
// so each flush is 32 x red.global.add.v2.f32 covering 256 contiguous bytes.
// Lane 0 additionally marks the voxel in the touched bitmap.
__global__ void __launch_bounds__(256) scatter_runs_kernel(
        const float* __restrict__ x) {
    int seg  = blockIdx.x / BLKS_PER_SEG;
    int sub  = blockIdx.x - seg * BLKS_PER_SEG;
    int cnt  = g_warp_count[seg];
    if (cnt == 0) return;
    const int2* runs = g_runs + seg * RUNS_PER_WARP2;
    int wrp  = threadIdx.x >> 5;
    int lane = threadIdx.x & 31;
    int gw   = sub * 8 + wrp;          // warps serving this segment
    const float2* xf2 = reinterpret_cast<const float2*>(x);

    for (int base = gw * CHUNK; base < cnt; base += BLKS_PER_SEG * 8 * CHUNK) {
        int n = min(CHUNK, cnt - base);

        // cooperative record fetch: lanes 0..7 each load one rec, broadcast
        int2 myrec = make_int2(0, -1);
        if (lane < n) myrec = __ldg(runs + base + lane);
        int rx[CHUNK], ry[CHUNK];
        #pragma unroll
        for (int i = 0; i < CHUNK; i++) {
            rx[i] = __shfl_sync(0xffffffffu, myrec.x, i);
            ry[i] = __shfl_sync(0xffffffffu, myrec.y, i);
        }

        // depth-major accumulation: level-j loads for all runs are independent
        float2 acc[CHUNK];
        #pragma unroll
        for (int i = 0; i < CHUNK; i++) acc[i] = make_float2(0.f, 0.f);

        #pragma unroll
        for (int j = 0; j < MAXRUN; j++) {
            float2 v[CHUNK];
            #pragma unroll
            for (int i = 0; i < CHUNK; i++) {
                int c = rx[i] >> 20;
                if (i < n && j < c) {
                    int p = (rx[i] & 0xFFFFF) + j * RAYS_PER_BN;
                    v[i] = __ldg(xf2 + (size_t)p * (CC/2) + lane);
                }
            }
            #pragma unroll
            for (int i = 0; i < CHUNK; i++) {
                int c = rx[i] >> 20;
                if (i < n && j < c) { acc[i].x += v[i].x; acc[i].y += v[i].y; }
            }
        }

        // merge consecutive same-voxel runs, then coalesced vector-red flush
        int curOff = -1;
        float2 a = make_float2(0.f, 0.f);
        #pragma unroll
        for (int i = 0; i < CHUNK; i++) {
            if (i >= n) break;
            if (ry[i] != curOff) {
                if (curOff >= 0) {
                    float* dp = g_scratch + (size_t)curOff * CC + 2*lane;
                    asm volatile("red.global.add.v2.f32 [%0], {%1, %2};"
                                 :: "l"(dp), "f"(a.x), "f"(a.y) : "memory");
                    if (lane == 0)
                        atomicOr(&g_bitmap[curOff >> 5], 1u << (curOff & 31));
                }
                curOff = ry[i];
                a = make_float2(0.f, 0.f);
            }
            a.x += acc[i].x; a.y += acc[i].y;
        }
        if (curOff >= 0) {
            float* dp = g_scratch + (size_t)curOff * CC + 2*lane;
            asm volatile("red.global.add.v2.f32 [%0], {%1, %2};"
                         :: "l"(dp), "f"(a.x), "f"(a.y) : "memory");
            if (lane == 0)
                atomicOr(&g_bitmap[curOff >> 5], 1u << (curOff & 31));
        }
    }
}

// ---------------- touched-tile writer: gather + cleanup (zeros pre-written) ----------------
// Tile untouched -> return immediately (out already zeroed by run_zero_kernel).
// Touched -> overwrite out with gathered scratch rows, re-zero scratch, clear word.
__global__ void __launch_bounds__(256) out_touched_kernel(float* __restrict__ out) {
    __shared__ unsigned sw;
    int b    = blockIdx.y;
    int tile = blockIdx.x;              // 0..1249
    int tid  = threadIdx.x;
    int lane = tid & 31;
    int wrp  = tid >> 5;                // 0..7

    if (tid == 0) sw = g_bitmap[b * WORDS_PER_B + tile];
    __syncthreads();
    unsigned word = sw;
    if (word == 0) return;              // zeros already in place

    int s0 = tile * 32;
    float* sc = g_scratch + ((size_t)b * SPATIAL + s0) * CC;

    float vals[8];
    if ((word >> lane) & 1u) {
        const float4* p = reinterpret_cast<const float4*>(sc + lane*CC + wrp*8);
        float4 v0 = p[0];
        float4 v1 = p[1];
        vals[0]=v0.x; vals[1]=v0.y; vals[2]=v0.z; vals[3]=v0.w;
        vals[4]=v1.x; vals[5]=v1.y; vals[6]=v1.z; vals[7]=v1.w;
    } else {
        #pragma unroll
        for (int k = 0; k < 8; k++) vals[k] = 0.f;
    }

    float* op = out + ((size_t)b * CC + wrp*8) * SPATIAL + s0 + lane;
    #pragma unroll
    for (int k = 0; k < 8; k++)
        op[(size_t)k * SPATIAL] = vals[k];

    __syncthreads();

    // re-zero touched scratch rows: thread t -> voxel t>>3, floats [(t&7)*8, +8)
    int vox = tid >> 3;
    if ((word >> vox) & 1u) {
        float4* p = reinterpret_cast<float4*>(sc + vox*CC + (tid & 7)*8);
        const float4 z4 = make_float4(0.f, 0.f, 0.f, 0.f);
        p[0] = z4;
        p[1] = z4;
    }
    if (tid == 0) g_bitmap[b * WORDS_PER_B + tile] = 0u;
}

// ---------------- launch ----------------
extern "C" void kernel_launch(void* const* d_in, const int* in_sizes, int n_in,
                              void* d_out, int out_size) {
    const float* x          = (const float*)d_in[0];
    const float* rots       = (const float*)d_in[1];
    const float* trans      = (const float*)d_in[2];
    const float* intrins    = (const float*)d_in[3];
    const float* post_rots  = (const float*)d_in[4];
    const float* post_trans = (const float*)d_in[5];
    float* out = (float*)d_out;

    // 1. fused: ray walk (264 blocks) + output zeroing (2560 blocks)
    run_zero_kernel<<<RUN_BLOCKS + ZERO_BLOCKS, 256>>>(
        rots, intrins, post_rots, trans, post_trans, (float4*)out);

    // 2. feature accumulate into channel-last scratch + bitmap marking
    scatter_runs_kernel<<<NWARPS2 * BLKS_PER_SEG, 256>>>(x);

    // 3. touched tiles only: gather scratch -> out, restore invariants
    out_touched_kernel<<<dim3(WORDS_PER_B, BB), 256>>>(out);
}